// round 14
// baseline (speedup 1.0000x reference)
#include <cuda_runtime.h>
#include <cuda_fp16.h>
#include <math.h>
#include <stdint.h>

// ---------------- problem constants ----------------
#define BB 2
#define TT 2048
#define DD 1024
#define HH 16
#define HD 64
#define STRIDE 8
#define MLPD 4096
#define BT (BB*TT)          // 4096 rows
#define D3 (3*DD)           // 3072
#define NS 4                // KV splits for attention
#define NGR 256             // global rows per batch (T/STRIDE)

// ---------------- scratch buffers ----------------
__device__ __half g_xn [BT*DD];
__device__ __half g_o  [BT*DD];
__device__ __half g_xn2[BT*DD];
__device__ __half g_h  [BT*MLPD];
__device__ __half g_win[D3*DD];
__device__ __half g_wout[DD*DD];
__device__ __half g_w1 [MLPD*DD];
__device__ __half g_w2 [DD*MLPD];
__device__ __half g_qkv[BT*D3];
__device__ float g_x2 [BT*DD];
__device__ float g_opart[BB*NGR*HH*NS*HD];
__device__ float g_mpart[BB*NGR*HH*NS];
__device__ float g_lpart[BB*NGR*HH*NS];

// ---------------- helpers ----------------
__device__ __forceinline__ uint32_t smem_u32(const void* p) {
    uint32_t a;
    asm("{ .reg .u64 t; cvta.to.shared.u64 t, %1; cvt.u32.u64 %0, t; }" : "=r"(a) : "l"(p));
    return a;
}
__device__ __forceinline__ void cp16(uint32_t dst, const void* src) {
    asm volatile("cp.async.cg.shared.global [%0], [%1], 16;" :: "r"(dst), "l"(src) : "memory");
}
__device__ __forceinline__ void ldmx4(uint32_t* r, uint32_t addr) {
    asm volatile("ldmatrix.sync.aligned.m8n8.x4.shared.b16 {%0,%1,%2,%3}, [%4];"
        : "=r"(r[0]), "=r"(r[1]), "=r"(r[2]), "=r"(r[3]) : "r"(addr));
}
__device__ __forceinline__ void ldmx4t(uint32_t* r, uint32_t addr) {
    asm volatile("ldmatrix.sync.aligned.m8n8.x4.trans.shared.b16 {%0,%1,%2,%3}, [%4];"
        : "=r"(r[0]), "=r"(r[1]), "=r"(r[2]), "=r"(r[3]) : "r"(addr));
}
__device__ __forceinline__ void mma_f16(float* c, const uint32_t* a, const uint32_t* b) {
    asm volatile("mma.sync.aligned.m16n8k16.row.col.f32.f16.f16.f32 "
        "{%0,%1,%2,%3}, {%4,%5,%6,%7}, {%8,%9}, {%0,%1,%2,%3};"
        : "+f"(c[0]), "+f"(c[1]), "+f"(c[2]), "+f"(c[3])
        : "r"(a[0]), "r"(a[1]), "r"(a[2]), "r"(a[3]), "r"(b[0]), "r"(b[1]));
}
__device__ __forceinline__ void cvt4(const float* __restrict__ src,
                                     __half* __restrict__ dst, int i) {
    float4 v = ((const float4*)src)[i];
    ((__half2*)dst)[2*i]   = __floats2half2_rn(v.x, v.y);
    ((__half2*)dst)[2*i+1] = __floats2half2_rn(v.z, v.w);
}

// ---------------- GEMM config: CTA 128x256, GK=64, 3-stage ----------------
#define GM 128
#define GN 256
#define GK 64
#define AT_B 16384
#define STAGE_B 49152
#define NST 3
#define GEMM_SMEM (NST*STAGE_B)

#define SWO(r, c) ((uint32_t)((r) * 128 + (((c) ^ ((r) & 7)) & 7) * 16))

#define GEMM_PROLOG() \
    float acc[4][8][4]; \
    _Pragma("unroll") \
    for (int i_ = 0; i_ < 4; i_++) \
        _Pragma("unroll") \
        for (int j_ = 0; j_ < 8; j_++) \
            _Pragma("unroll") \
            for (int k_ = 0; k_ < 4; k_++) acc[i_][j_][k_] = 0.f; \
    const int la_row = lane & 15; \
    const int la_kh  = lane >> 4; \
    const int lb_row = (lane & 7) + ((lane >> 4) << 3); \
    const int lb_kh  = (lane >> 3) & 1;

#define GEMM_MAINLOOP(nch) \
    load_stage(0, 0); \
    load_stage(1, 1); \
    for (int i = 0; i < (nch); i++) { \
        asm volatile("cp.async.wait_group 1;" ::: "memory"); \
        __syncthreads(); \
        if (i + 2 < (nch)) load_stage(i + 2, (i + 2) % NST); \
        else asm volatile("cp.async.commit_group;" ::: "memory"); \
        const uint32_t aB = sb + (i % NST) * STAGE_B; \
        const uint32_t wB = aB + AT_B; \
        _Pragma("unroll") \
        for (int ks = 0; ks < 4; ks++) { \
            uint32_t b4[4][4]; \
            _Pragma("unroll") \
            for (int nf2 = 0; nf2 < 4; nf2++) { \
                const int r = wn + nf2 * 16 + lb_row; \
                ldmx4(b4[nf2], wB + SWO(r, ks * 2 + lb_kh)); \
            } \
            _Pragma("unroll") \
            for (int mf = 0; mf < 4; mf++) { \
                uint32_t a_[4]; \
                const int r = wm + mf * 16 + la_row; \
                ldmx4(a_, aB + SWO(r, ks * 2 + la_kh)); \
                _Pragma("unroll") \
                for (int nf2 = 0; nf2 < 4; nf2++) { \
                    mma_f16(acc[mf][2 * nf2 + 0], a_, &b4[nf2][0]); \
                    mma_f16(acc[mf][2 * nf2 + 1], a_, &b4[nf2][2]); \
                } \
            } \
        } \
    }

// ---------------- generic GEMM ----------------
template<bool GELU_, bool RES_, bool F16O_>
__global__ void __launch_bounds__(256, 1) gemm_f16k(
    const __half* __restrict__ A, const __half* __restrict__ W,
    const float* __restrict__ bias, const float* __restrict__ Rres,
    float* __restrict__ C, __half* __restrict__ Cf, int N, int K)
{
    extern __shared__ char smem[];
    const uint32_t sb = smem_u32(smem);
    const int t = threadIdx.x;
    const int wid = t >> 5, lane = t & 31;
    const int m0 = blockIdx.y * GM;
    const int n0 = blockIdx.x * GN;
    const int wm = (wid & 1) * 64;
    const int wn = (wid >> 1) * 64;
    const int nch = K / GK;

    auto load_stage = [&](int chunk, int s) {
        const uint32_t base = sb + s * STAGE_B;
        #pragma unroll
        for (int j = 0; j < 4; j++) {
            const int idx = t + j * 256;
            const int r = idx >> 3, c = idx & 7;
            cp16(base + SWO(r, c), A + (size_t)(m0 + r) * K + (size_t)chunk * GK + c * 8);
        }
        #pragma unroll
        for (int j = 0; j < 8; j++) {
            const int idx = t + j * 256;
            const int r = idx >> 3, c = idx & 7;
            cp16(base + AT_B + SWO(r, c), W + (size_t)(n0 + r) * K + (size_t)chunk * GK + c * 8);
        }
        asm volatile("cp.async.commit_group;" ::: "memory");
    };

    GEMM_PROLOG();
    GEMM_MAINLOOP(nch);

    const int er = lane >> 2;
    const int ec = (lane & 3) * 2;
    #pragma unroll
    for (int mf = 0; mf < 4; mf++) {
        #pragma unroll
        for (int nf = 0; nf < 8; nf++) {
            const int c0 = n0 + wn + nf * 8 + ec;
            const float b0 = bias[c0], b1 = bias[c0 + 1];
            #pragma unroll
            for (int half = 0; half < 2; half++) {
                const int r = m0 + wm + mf * 16 + er + half * 8;
                float v0 = acc[mf][nf][half * 2 + 0] + b0;
                float v1 = acc[mf][nf][half * 2 + 1] + b1;
                if (GELU_) {
                    v0 = 0.5f * v0 * (1.0f + erff(v0 * 0.70710678118654752f));
                    v1 = 0.5f * v1 * (1.0f + erff(v1 * 0.70710678118654752f));
                }
                if (RES_) {
                    v0 += Rres[(size_t)r * N + c0];
                    v1 += Rres[(size_t)r * N + c0 + 1];
                }
                if (F16O_) {
                    *(__half2*)(Cf + (size_t)r * N + c0) = __floats2half2_rn(v0, v1);
                } else {
                    float2 p; p.x = v0; p.y = v1;
                    *(float2*)(C + (size_t)r * N + c0) = p;
                }
            }
        }
    }
}

// ---------------- QKV kernel (+ hidden weight conversion in idle blocks) ---
#define CVO (DD*DD/4)          // w_out chunks
#define CV1N (MLPD*DD/4)       // w1 chunks
#define CV2N (DD*MLPD/4)       // w2 chunks
#define CVT_TOTAL (CVO + CV1N + CV2N)
#define CVT_NT (4*28*256)      // threads in the idle-block pool

__global__ void __launch_bounds__(256, 1) qkv_kernel(
    const __half* __restrict__ Axn, const __half* __restrict__ win,
    const float* __restrict__ b_in, __half* __restrict__ qkv,
    __half* __restrict__ o,
    const float* __restrict__ w_out_f, __half* __restrict__ wout_h,
    const float* __restrict__ w1_f,    __half* __restrict__ w1_h,
    const float* __restrict__ w2_f,    __half* __restrict__ w2_h)
{
    const bool kvb = blockIdx.x < 8;
    const int t = threadIdx.x;
    if (!kvb && blockIdx.y >= 4) {
        // idle q-blocks: convert w_out / w1 / w2 to fp16
        const int gid = (((int)blockIdx.x - 8) * 28 + ((int)blockIdx.y - 4)) * 256 + t;
        for (int i = gid; i < CVT_TOTAL; i += CVT_NT) {
            if (i < CVO)              cvt4(w_out_f, wout_h, i);
            else if (i < CVO + CV1N)  cvt4(w1_f,    w1_h,   i - CVO);
            else                      cvt4(w2_f,    w2_h,   i - CVO - CV1N);
        }
        return;
    }
    extern __shared__ char smem[];
    const uint32_t sb = smem_u32(smem);
    const int wid = t >> 5, lane = t & 31;
    const int bx = kvb ? blockIdx.x : blockIdx.x - 8;
    const int rs = kvb ? 1 : 8;
    const int colOff = kvb ? 1024 : 0;
    const int m0 = blockIdx.y * GM;
    const int n0 = bx * GN;
    const int wm = (wid & 1) * 64;
    const int wn = (wid >> 1) * 64;
    const int K = DD;
    const int nch = K / GK;
    const __half* W = win + (size_t)(colOff + n0) * K;

    auto load_stage = [&](int chunk, int s) {
        const uint32_t base = sb + s * STAGE_B;
        #pragma unroll
        for (int j = 0; j < 4; j++) {
            const int idx = t + j * 256;
            const int r = idx >> 3, c = idx & 7;
            cp16(base + SWO(r, c), Axn + (size_t)((m0 + r) * rs) * K + (size_t)chunk * GK + c * 8);
        }
        #pragma unroll
        for (int j = 0; j < 8; j++) {
            const int idx = t + j * 256;
            const int r = idx >> 3, c = idx & 7;
            cp16(base + AT_B + SWO(r, c), W + (size_t)r * K + (size_t)chunk * GK + c * 8);
        }
        asm volatile("cp.async.commit_group;" ::: "memory");
    };

    GEMM_PROLOG();
    GEMM_MAINLOOP(nch);

    const bool vblk = kvb && (bx >= 4);
    const int er = lane >> 2;
    const int ec = (lane & 3) * 2;
    #pragma unroll
    for (int mf = 0; mf < 4; mf++) {
        #pragma unroll
        for (int nf = 0; nf < 8; nf++) {
            const int g = colOff + n0 + wn + nf * 8 + ec;
            const float b0 = b_in[g], b1 = b_in[g + 1];
            #pragma unroll
            for (int half = 0; half < 2; half++) {
                const int r = (m0 + wm + mf * 16 + er + half * 8) * rs;
                const __half2 hv = __floats2half2_rn(
                    acc[mf][nf][half * 2 + 0] + b0,
                    acc[mf][nf][half * 2 + 1] + b1);
                *(__half2*)(qkv + (size_t)r * D3 + g) = hv;
                if (vblk && ((r & (TT - 1)) & (STRIDE - 1)) != 0)
                    *(__half2*)(o + (size_t)r * DD + g - 2048) = hv;
            }
        }
    }
}

// ---------------- LayerNorm -> f16 (+ optional weight convert) ------------
__global__ __launch_bounds__(256) void ln_f16_kernel(
    const float* __restrict__ x, const float* __restrict__ g, const float* __restrict__ b,
    __half* __restrict__ y, const float* __restrict__ wsrc,
    __half* __restrict__ wdst, int wn4)
{
    const int row = blockIdx.x;
    const int tid = threadIdx.x;
    float4 v = ((const float4*)(x + (size_t)row * DD))[tid];

    float s  = v.x + v.y + v.z + v.w;
    float sq = v.x*v.x + v.y*v.y + v.z*v.z + v.w*v.w;
    __shared__ float red_s[8], red_q[8];
    for (int o = 16; o > 0; o >>= 1) {
        s  += __shfl_xor_sync(0xffffffffu, s,  o);
        sq += __shfl_xor_sync(0xffffffffu, sq, o);
    }
    const int wid = tid >> 5, lid = tid & 31;
    if (lid == 0) { red_s[wid] = s; red_q[wid] = sq; }
    __syncthreads();
    if (tid == 0) {
        float ts = 0.f, tq = 0.f;
        #pragma unroll
        for (int i = 0; i < 8; i++) { ts += red_s[i]; tq += red_q[i]; }
        red_s[0] = ts * (1.0f / DD);
        red_q[0] = tq * (1.0f / DD);
    }
    __syncthreads();
    const float mean = red_s[0];
    const float rstd = rsqrtf(red_q[0] - mean * mean + 1e-5f);

    const float4 gg = ((const float4*)g)[tid];
    const float4 bb = ((const float4*)b)[tid];
    float o0 = (v.x - mean) * rstd * gg.x + bb.x;
    float o1 = (v.y - mean) * rstd * gg.y + bb.y;
    float o2 = (v.z - mean) * rstd * gg.z + bb.z;
    float o3 = (v.w - mean) * rstd * gg.w + bb.w;
    __half2* py = (__half2*)(y + (size_t)row * DD);
    py[2*tid]   = __floats2half2_rn(o0, o1);
    py[2*tid+1] = __floats2half2_rn(o2, o3);

    // side job: fp32->fp16 weight conversion (strided over whole grid)
    if (wn4 > 0) {
        for (int i = row * 256 + tid; i < wn4; i += gridDim.x * 256)
            cvt4(wsrc, wdst, i);
    }
}

// ---------------- FA2-style split-KV HMMA attention ----------------
#define AQ 64
#define CK 64
#define QS_B (AQ*144)
#define KV_B (CK*144)
#define KS_OFF QS_B
#define VS_OFF (KS_OFF + 2*KV_B)
#define ATTN_SMEM (VS_OFF + 2*KV_B)     // 46080
#define KEYS_PER_SPLIT (TT / NS)        // 512
#define CHPS (KEYS_PER_SPLIT / CK)      // 8

__global__ void __launch_bounds__(128, 4) attn_hmma_kernel(
    float* __restrict__ o_part, float* __restrict__ m_part,
    float* __restrict__ l_part, const __half* __restrict__ qkv)
{
    extern __shared__ char smem[];
    const uint32_t sb = smem_u32(smem);

    const int t = threadIdx.x;
    const int w = t >> 5, lane = t & 31;
    const int blk = blockIdx.x;
    const int sp = blk & (NS - 1);
    const int qt = (blk >> 2) & 3;
    const int h  = (blk >> 4) & (HH - 1);
    const int b  = blk >> 8;

    {
        const __half2 sc = __floats2half2_rn(0.125f, 0.125f);
        #pragma unroll
        for (int j = 0; j < 4; j++) {
            const int idx = t + j * 128;
            const int q = idx >> 3, c = idx & 7;
            const int tq = (qt * AQ + q) * STRIDE;
            uint4 raw = *(const uint4*)(qkv + (size_t)(b * TT + tq) * D3 + h * HD + c * 8);
            __half2* hp = (__half2*)&raw;
            #pragma unroll
            for (int u = 0; u < 4; u++) hp[u] = __hmul2(hp[u], sc);
            *(uint4*)(smem + q * 144 + c * 16) = raw;
        }
    }
    __syncthreads();

    uint32_t aq[4][4];
    {
        const int r = w * 16 + (lane & 15);
        #pragma unroll
        for (int ks = 0; ks < 4; ks++)
            ldmx4(aq[ks], sb + (uint32_t)(r * 144) + (ks * 2 + (lane >> 4)) * 16);
    }

    auto load_kv = [&](int k0, int s) {
        const uint32_t kb = sb + KS_OFF + s * KV_B;
        const uint32_t vb = sb + VS_OFF + s * KV_B;
        #pragma unroll
        for (int j = 0; j < 4; j++) {
            const int idx = t + j * 128;
            const int r = idx >> 3, c = idx & 7;
            const size_t g = (size_t)(b * TT + k0 + r) * D3 + h * HD + c * 8;
            cp16(kb + r * 144 + c * 16, qkv + DD + g);
            cp16(vb + r * 144 + c * 16, qkv + 2 * DD + g);
        }
        asm volatile("cp.async.commit_group;" ::: "memory");
    };

    float oacc[8][4];
    #pragma unroll
    for (int i = 0; i < 8; i++)
        #pragma unroll
        for (int j = 0; j < 4; j++) oacc[i][j] = 0.f;
    float m0 = -1e30f, m1 = -1e30f, l0 = 0.f, l1 = 0.f;

    const int k0base = sp * KEYS_PER_SPLIT;
    load_kv(k0base, 0);

    const int lb_row = (lane & 7) + ((lane >> 4) << 3);
    const int lb_kh  = (lane >> 3) & 1;
    const int vrow   = (lane & 7) + ((lane >> 3) & 1) * 8;
    const int vcol   = (lane >> 4) * 8;

    for (int cc = 0; cc < CHPS; cc++) {
        if (cc + 1 < CHPS) load_kv(k0base + (cc + 1) * CK, (cc + 1) & 1);
        else asm volatile("cp.async.commit_group;" ::: "memory");
        asm volatile("cp.async.wait_group 1;" ::: "memory");
        __syncthreads();
        const uint32_t kB = sb + KS_OFF + (cc & 1) * KV_B;
        const uint32_t vB = sb + VS_OFF + (cc & 1) * KV_B;

        // ---- S = Q K^T
        float sacc[8][4];
        #pragma unroll
        for (int i = 0; i < 8; i++)
            #pragma unroll
            for (int j = 0; j < 4; j++) sacc[i][j] = 0.f;
        #pragma unroll
        for (int ks = 0; ks < 4; ks++) {
            uint32_t b4[4][4];
            #pragma unroll
            for (int nf2 = 0; nf2 < 4; nf2++) {
                const int r = nf2 * 16 + lb_row;
                ldmx4(b4[nf2], kB + (uint32_t)(r * 144) + (ks * 2 + lb_kh) * 16);
            }
            #pragma unroll
            for (int nf2 = 0; nf2 < 4; nf2++) {
                mma_f16(sacc[2 * nf2 + 0], aq[ks], &b4[nf2][0]);
                mma_f16(sacc[2 * nf2 + 1], aq[ks], &b4[nf2][2]);
            }
        }

        // ---- register online softmax
        float mx0 = -1e30f, mx1 = -1e30f;
        #pragma unroll
        for (int nf = 0; nf < 8; nf++) {
            mx0 = fmaxf(mx0, fmaxf(sacc[nf][0], sacc[nf][1]));
            mx1 = fmaxf(mx1, fmaxf(sacc[nf][2], sacc[nf][3]));
        }
        mx0 = fmaxf(mx0, __shfl_xor_sync(0xffffffffu, mx0, 1));
        mx0 = fmaxf(mx0, __shfl_xor_sync(0xffffffffu, mx0, 2));
        mx1 = fmaxf(mx1, __shfl_xor_sync(0xffffffffu, mx1, 1));
        mx1 = fmaxf(mx1, __shfl_xor_sync(0xffffffffu, mx1, 2));
        const float mn0 = fmaxf(m0, mx0);
        const float mn1 = fmaxf(m1, mx1);
        const float cr0 = __expf(m0 - mn0);
        const float cr1 = __expf(m1 - mn1);
        m0 = mn0; m1 = mn1;

        float ls0 = 0.f, ls1 = 0.f;
        uint32_t ap[4][4];
        #pragma unroll
        for (int kp = 0; kp < 4; kp++) {
            #pragma unroll
            for (int half = 0; half < 2; half++) {
                const int nf = 2 * kp + half;
                float e0 = __expf(sacc[nf][0] - mn0);
                float e1 = __expf(sacc[nf][1] - mn0);
                float e2 = __expf(sacc[nf][2] - mn1);
                float e3 = __expf(sacc[nf][3] - mn1);
                ls0 += e0 + e1; ls1 += e2 + e3;
                __half2 p01 = __floats2half2_rn(e0, e1);
                __half2 p23 = __floats2half2_rn(e2, e3);
                ap[kp][2 * half + 0] = *(uint32_t*)&p01;
                ap[kp][2 * half + 1] = *(uint32_t*)&p23;
            }
        }
        ls0 += __shfl_xor_sync(0xffffffffu, ls0, 1);
        ls0 += __shfl_xor_sync(0xffffffffu, ls0, 2);
        ls1 += __shfl_xor_sync(0xffffffffu, ls1, 1);
        ls1 += __shfl_xor_sync(0xffffffffu, ls1, 2);
        l0 = l0 * cr0 + ls0;
        l1 = l1 * cr1 + ls1;

        #pragma unroll
        for (int nf = 0; nf < 8; nf++) {
            oacc[nf][0] *= cr0; oacc[nf][1] *= cr0;
            oacc[nf][2] *= cr1; oacc[nf][3] *= cr1;
        }

        // ---- O += P V
        #pragma unroll
        for (int kp = 0; kp < 4; kp++) {
            const int krow = kp * 16 + vrow;
            #pragma unroll
            for (int nf2 = 0; nf2 < 4; nf2++) {
                uint32_t bv[4];
                ldmx4t(bv, vB + (uint32_t)(krow * 144) + (nf2 * 16 + vcol) * 2);
                mma_f16(oacc[2 * nf2 + 0], ap[kp], &bv[0]);
                mma_f16(oacc[2 * nf2 + 1], ap[kp], &bv[2]);
            }
        }
        __syncthreads();
    }

    {
        const int r0 = w * 16 + (lane >> 2);
        const int r1 = r0 + 8;
        #pragma unroll
        for (int nf = 0; nf < 8; nf++) {
            const int d = nf * 8 + (lane & 3) * 2;
            const size_t i0 = ((((size_t)(b * NGR + qt * AQ + r0)) * HH + h) * NS + sp) * HD + d;
            const size_t i1 = ((((size_t)(b * NGR + qt * AQ + r1)) * HH + h) * NS + sp) * HD + d;
            float2 p0; p0.x = oacc[nf][0]; p0.y = oacc[nf][1];
            float2 p1; p1.x = oacc[nf][2]; p1.y = oacc[nf][3];
            *(float2*)(o_part + i0) = p0;
            *(float2*)(o_part + i1) = p1;
        }
        if ((lane & 3) == 0) {
            const size_t mi0 = (((size_t)(b * NGR + qt * AQ + r0)) * HH + h) * NS + sp;
            const size_t mi1 = (((size_t)(b * NGR + qt * AQ + r1)) * HH + h) * NS + sp;
            m_part[mi0] = m0; l_part[mi0] = l0;
            m_part[mi1] = m1; l_part[mi1] = l1;
        }
    }
}

// ---------------- attention split reduce ----------------
__global__ __launch_bounds__(256) void attn_reduce_kernel(
    __half* __restrict__ o, const float* __restrict__ o_part,
    const float* __restrict__ m_part, const float* __restrict__ l_part)
{
    const int idx = blockIdx.x * 256 + threadIdx.x;
    const int d  = idx & (HD - 1);
    const int rh = idx >> 6;
    const int h  = rh & (HH - 1);
    const int br = rh >> 4;
    const size_t mb = (size_t)rh * NS;

    float m0 = m_part[mb], m1 = m_part[mb+1], m2 = m_part[mb+2], m3 = m_part[mb+3];
    float mx = fmaxf(fmaxf(m0, m1), fmaxf(m2, m3));
    float w0 = __expf(m0 - mx), w1 = __expf(m1 - mx), w2 = __expf(m2 - mx), w3 = __expf(m3 - mx);
    float lsum = w0 * l_part[mb] + w1 * l_part[mb+1] + w2 * l_part[mb+2] + w3 * l_part[mb+3];
    const size_t ob = (size_t)rh * NS * HD + d;
    float val = w0 * o_part[ob] + w1 * o_part[ob + HD]
              + w2 * o_part[ob + 2*HD] + w3 * o_part[ob + 3*HD];
    val /= lsum;
    const int b = br >> 8;
    const int row = br & (NGR - 1);
    o[(size_t)(b * TT + row * STRIDE) * DD + h * HD + d] = __float2half(val);
}

// ---------------- launch ----------------
extern "C" void kernel_launch(void* const* d_in, const int* in_sizes, int n_in,
                              void* d_out, int out_size)
{
    const float* x     = (const float*)d_in[0];
    const float* w_in  = (const float*)d_in[1];
    const float* b_in  = (const float*)d_in[2];
    const float* w_out = (const float*)d_in[3];
    const float* b_out = (const float*)d_in[4];
    const float* w1    = (const float*)d_in[5];
    const float* b1    = (const float*)d_in[6];
    const float* w2    = (const float*)d_in[7];
    const float* b2    = (const float*)d_in[8];
    const float* ln1_g = (const float*)d_in[9];
    const float* ln1_b = (const float*)d_in[10];
    const float* ln2_g = (const float*)d_in[11];
    const float* ln2_b = (const float*)d_in[12];
    float* out = (float*)d_out;

    __half *xn,*o,*xn2,*hbuf,*win,*wout,*w1h,*w2h,*qkv;
    float *x2, *opart, *mpart, *lpart;
    cudaGetSymbolAddress((void**)&xn,   g_xn);
    cudaGetSymbolAddress((void**)&o,    g_o);
    cudaGetSymbolAddress((void**)&xn2,  g_xn2);
    cudaGetSymbolAddress((void**)&hbuf, g_h);
    cudaGetSymbolAddress((void**)&win,  g_win);
    cudaGetSymbolAddress((void**)&wout, g_wout);
    cudaGetSymbolAddress((void**)&w1h,  g_w1);
    cudaGetSymbolAddress((void**)&w2h,  g_w2);
    cudaGetSymbolAddress((void**)&qkv,  g_qkv);
    cudaGetSymbolAddress((void**)&x2,   g_x2);
    cudaGetSymbolAddress((void**)&opart, g_opart);
    cudaGetSymbolAddress((void**)&mpart, g_mpart);
    cudaGetSymbolAddress((void**)&lpart, g_lpart);

    cudaFuncSetAttribute(qkv_kernel, cudaFuncAttributeMaxDynamicSharedMemorySize, GEMM_SMEM);
    cudaFuncSetAttribute(gemm_f16k<false,true ,false>, cudaFuncAttributeMaxDynamicSharedMemorySize, GEMM_SMEM);
    cudaFuncSetAttribute(gemm_f16k<true ,false,true >, cudaFuncAttributeMaxDynamicSharedMemorySize, GEMM_SMEM);
    cudaFuncSetAttribute(attn_hmma_kernel, cudaFuncAttributeMaxDynamicSharedMemorySize, ATTN_SMEM);

    // 1. LN1 -> f16 (+ convert w_in in spare cycles)
    ln_f16_kernel<<<BT, 256>>>(x, ln1_g, ln1_b, xn, w_in, win, D3*DD/4);
    // 2. QKV (kv: all rows; q: global rows; idle blocks convert w_out/w1/w2)
    qkv_kernel<<<dim3(12, 32), 256, GEMM_SMEM>>>(xn, win, b_in, qkv, o,
                                                 w_out, wout, w1, w1h, w2, w2h);
    // 3. attention: FA2 split-KV partials + reduce
    attn_hmma_kernel<<<BB*HH*4*NS, 128, ATTN_SMEM>>>(opart, mpart, lpart, qkv);
    attn_reduce_kernel<<<(BB*NGR*HH*HD)/256, 256>>>(o, opart, mpart, lpart);
    // 4. out-proj + residual -> x2 fp32
    gemm_f16k<false,true,false><<<dim3(DD/GN, BT/GM), 256, GEMM_SMEM>>>(
        o, wout, b_out, x, x2, nullptr, DD, DD);
    // 5. LN2 -> f16
    ln_f16_kernel<<<BT, 256>>>(x2, ln2_g, ln2_b, xn2, nullptr, nullptr, 0);
    // 6. MLP1 + GELU -> h f16
    gemm_f16k<true,false,true><<<dim3(MLPD/GN, BT/GM), 256, GEMM_SMEM>>>(
        xn2, w1h, b1, nullptr, nullptr, hbuf, MLPD, DD);
    // 7. MLP2 + residual -> out fp32
    gemm_f16k<false,true,false><<<dim3(DD/GN, BT/GM), 256, GEMM_SMEM>>>(
        hbuf, w2h, b2, x2, out, nullptr, DD, MLPD);
}

// round 15
// speedup vs baseline: 1.1016x; 1.1016x over previous
#include <cuda_runtime.h>
#include <cuda_fp16.h>
#include <math.h>
#include <stdint.h>

// ---------------- problem constants ----------------
#define BB 2
#define TT 2048
#define DD 1024
#define HH 16
#define HD 64
#define STRIDE 8
#define MLPD 4096
#define BT (BB*TT)          // 4096 rows
#define D3 (3*DD)           // 3072
#define NS 4                // KV splits for attention
#define NGR 256             // global rows per batch (T/STRIDE)

// ---------------- scratch buffers ----------------
__device__ __half g_xn [BT*DD];
__device__ __half g_o  [BT*DD];
__device__ __half g_xn2[BT*DD];
__device__ __half g_h  [BT*MLPD];
__device__ __half g_win[D3*DD];
__device__ __half g_wout[DD*DD];
__device__ __half g_w1 [MLPD*DD];
__device__ __half g_w2 [DD*MLPD];
__device__ __half g_qkv[BT*D3];
__device__ float g_x2 [BT*DD];
__device__ float g_opart[BB*NGR*HH*NS*HD];
__device__ float g_mpart[BB*NGR*HH*NS];
__device__ float g_lpart[BB*NGR*HH*NS];

// ---------------- helpers ----------------
__device__ __forceinline__ uint32_t smem_u32(const void* p) {
    uint32_t a;
    asm("{ .reg .u64 t; cvta.to.shared.u64 t, %1; cvt.u32.u64 %0, t; }" : "=r"(a) : "l"(p));
    return a;
}
__device__ __forceinline__ void cp16(uint32_t dst, const void* src) {
    asm volatile("cp.async.cg.shared.global [%0], [%1], 16;" :: "r"(dst), "l"(src) : "memory");
}
__device__ __forceinline__ void ldmx4(uint32_t* r, uint32_t addr) {
    asm volatile("ldmatrix.sync.aligned.m8n8.x4.shared.b16 {%0,%1,%2,%3}, [%4];"
        : "=r"(r[0]), "=r"(r[1]), "=r"(r[2]), "=r"(r[3]) : "r"(addr));
}
__device__ __forceinline__ void ldmx4t(uint32_t* r, uint32_t addr) {
    asm volatile("ldmatrix.sync.aligned.m8n8.x4.trans.shared.b16 {%0,%1,%2,%3}, [%4];"
        : "=r"(r[0]), "=r"(r[1]), "=r"(r[2]), "=r"(r[3]) : "r"(addr));
}
__device__ __forceinline__ void mma_f16(float* c, const uint32_t* a, const uint32_t* b) {
    asm volatile("mma.sync.aligned.m16n8k16.row.col.f32.f16.f16.f32 "
        "{%0,%1,%2,%3}, {%4,%5,%6,%7}, {%8,%9}, {%0,%1,%2,%3};"
        : "+f"(c[0]), "+f"(c[1]), "+f"(c[2]), "+f"(c[3])
        : "r"(a[0]), "r"(a[1]), "r"(a[2]), "r"(a[3]), "r"(b[0]), "r"(b[1]));
}

// ---------------- GEMM config: CTA 128x256, GK=64, 3-stage ----------------
#define GM 128
#define GN 256
#define GK 64
#define AT_B 16384
#define STAGE_B 49152
#define NST 3
#define GEMM_SMEM (NST*STAGE_B)

#define SWO(r, c) ((uint32_t)((r) * 128 + (((c) ^ ((r) & 7)) & 7) * 16))

#define GEMM_PROLOG() \
    float acc[4][8][4]; \
    _Pragma("unroll") \
    for (int i_ = 0; i_ < 4; i_++) \
        _Pragma("unroll") \
        for (int j_ = 0; j_ < 8; j_++) \
            _Pragma("unroll") \
            for (int k_ = 0; k_ < 4; k_++) acc[i_][j_][k_] = 0.f; \
    const int la_row = lane & 15; \
    const int la_kh  = lane >> 4; \
    const int lb_row = (lane & 7) + ((lane >> 4) << 3); \
    const int lb_kh  = (lane >> 3) & 1;

#define GEMM_MAINLOOP(nch) \
    load_stage(0, 0); \
    load_stage(1, 1); \
    for (int i = 0; i < (nch); i++) { \
        asm volatile("cp.async.wait_group 1;" ::: "memory"); \
        __syncthreads(); \
        if (i + 2 < (nch)) load_stage(i + 2, (i + 2) % NST); \
        else asm volatile("cp.async.commit_group;" ::: "memory"); \
        const uint32_t aB = sb + (i % NST) * STAGE_B; \
        const uint32_t wB = aB + AT_B; \
        _Pragma("unroll") \
        for (int ks = 0; ks < 4; ks++) { \
            uint32_t b4[4][4]; \
            _Pragma("unroll") \
            for (int nf2 = 0; nf2 < 4; nf2++) { \
                const int r = wn + nf2 * 16 + lb_row; \
                ldmx4(b4[nf2], wB + SWO(r, ks * 2 + lb_kh)); \
            } \
            _Pragma("unroll") \
            for (int mf = 0; mf < 4; mf++) { \
                uint32_t a_[4]; \
                const int r = wm + mf * 16 + la_row; \
                ldmx4(a_, aB + SWO(r, ks * 2 + la_kh)); \
                _Pragma("unroll") \
                for (int nf2 = 0; nf2 < 4; nf2++) { \
                    mma_f16(acc[mf][2 * nf2 + 0], a_, &b4[nf2][0]); \
                    mma_f16(acc[mf][2 * nf2 + 1], a_, &b4[nf2][2]); \
                } \
            } \
        } \
    }

// ---------------- generic GEMM ----------------
template<bool GELU_, bool RES_, bool F16O_>
__global__ void __launch_bounds__(256, 1) gemm_f16k(
    const __half* __restrict__ A, const __half* __restrict__ W,
    const float* __restrict__ bias, const float* __restrict__ Rres,
    float* __restrict__ C, __half* __restrict__ Cf, int N, int K)
{
    extern __shared__ char smem[];
    const uint32_t sb = smem_u32(smem);
    const int t = threadIdx.x;
    const int wid = t >> 5, lane = t & 31;
    const int m0 = blockIdx.y * GM;
    const int n0 = blockIdx.x * GN;
    const int wm = (wid & 1) * 64;
    const int wn = (wid >> 1) * 64;
    const int nch = K / GK;

    auto load_stage = [&](int chunk, int s) {
        const uint32_t base = sb + s * STAGE_B;
        #pragma unroll
        for (int j = 0; j < 4; j++) {
            const int idx = t + j * 256;
            const int r = idx >> 3, c = idx & 7;
            cp16(base + SWO(r, c), A + (size_t)(m0 + r) * K + (size_t)chunk * GK + c * 8);
        }
        #pragma unroll
        for (int j = 0; j < 8; j++) {
            const int idx = t + j * 256;
            const int r = idx >> 3, c = idx & 7;
            cp16(base + AT_B + SWO(r, c), W + (size_t)(n0 + r) * K + (size_t)chunk * GK + c * 8);
        }
        asm volatile("cp.async.commit_group;" ::: "memory");
    };

    GEMM_PROLOG();
    GEMM_MAINLOOP(nch);

    const int er = lane >> 2;
    const int ec = (lane & 3) * 2;
    #pragma unroll
    for (int mf = 0; mf < 4; mf++) {
        #pragma unroll
        for (int nf = 0; nf < 8; nf++) {
            const int c0 = n0 + wn + nf * 8 + ec;
            const float b0 = bias[c0], b1 = bias[c0 + 1];
            #pragma unroll
            for (int half = 0; half < 2; half++) {
                const int r = m0 + wm + mf * 16 + er + half * 8;
                float v0 = acc[mf][nf][half * 2 + 0] + b0;
                float v1 = acc[mf][nf][half * 2 + 1] + b1;
                if (GELU_) {
                    v0 = 0.5f * v0 * (1.0f + erff(v0 * 0.70710678118654752f));
                    v1 = 0.5f * v1 * (1.0f + erff(v1 * 0.70710678118654752f));
                }
                if (RES_) {
                    v0 += Rres[(size_t)r * N + c0];
                    v1 += Rres[(size_t)r * N + c0 + 1];
                }
                if (F16O_) {
                    *(__half2*)(Cf + (size_t)r * N + c0) = __floats2half2_rn(v0, v1);
                } else {
                    float2 p; p.x = v0; p.y = v1;
                    *(float2*)(C + (size_t)r * N + c0) = p;
                }
            }
        }
    }
}

// ---------------- QKV kernel ----------------
__global__ void __launch_bounds__(256, 1) qkv_kernel(
    const __half* __restrict__ Axn, const __half* __restrict__ win,
    const float* __restrict__ b_in, __half* __restrict__ qkv,
    __half* __restrict__ o)
{
    const bool kvb = blockIdx.x < 8;
    if (!kvb && blockIdx.y >= 4) return;
    extern __shared__ char smem[];
    const uint32_t sb = smem_u32(smem);
    const int t = threadIdx.x;
    const int wid = t >> 5, lane = t & 31;
    const int bx = kvb ? blockIdx.x : blockIdx.x - 8;
    const int rs = kvb ? 1 : 8;
    const int colOff = kvb ? 1024 : 0;
    const int m0 = blockIdx.y * GM;
    const int n0 = bx * GN;
    const int wm = (wid & 1) * 64;
    const int wn = (wid >> 1) * 64;
    const int K = DD;
    const int nch = K / GK;
    const __half* W = win + (size_t)(colOff + n0) * K;

    auto load_stage = [&](int chunk, int s) {
        const uint32_t base = sb + s * STAGE_B;
        #pragma unroll
        for (int j = 0; j < 4; j++) {
            const int idx = t + j * 256;
            const int r = idx >> 3, c = idx & 7;
            cp16(base + SWO(r, c), Axn + (size_t)((m0 + r) * rs) * K + (size_t)chunk * GK + c * 8);
        }
        #pragma unroll
        for (int j = 0; j < 8; j++) {
            const int idx = t + j * 256;
            const int r = idx >> 3, c = idx & 7;
            cp16(base + AT_B + SWO(r, c), W + (size_t)r * K + (size_t)chunk * GK + c * 8);
        }
        asm volatile("cp.async.commit_group;" ::: "memory");
    };

    GEMM_PROLOG();
    GEMM_MAINLOOP(nch);

    const bool vblk = kvb && (bx >= 4);
    const int er = lane >> 2;
    const int ec = (lane & 3) * 2;
    #pragma unroll
    for (int mf = 0; mf < 4; mf++) {
        #pragma unroll
        for (int nf = 0; nf < 8; nf++) {
            const int g = colOff + n0 + wn + nf * 8 + ec;
            const float b0 = b_in[g], b1 = b_in[g + 1];
            #pragma unroll
            for (int half = 0; half < 2; half++) {
                const int r = (m0 + wm + mf * 16 + er + half * 8) * rs;
                const __half2 hv = __floats2half2_rn(
                    acc[mf][nf][half * 2 + 0] + b0,
                    acc[mf][nf][half * 2 + 1] + b1);
                *(__half2*)(qkv + (size_t)r * D3 + g) = hv;
                if (vblk && ((r & (TT - 1)) & (STRIDE - 1)) != 0)
                    *(__half2*)(o + (size_t)r * DD + g - 2048) = hv;
            }
        }
    }
}

// ---------------- LayerNorm -> f16 ----------------
__global__ __launch_bounds__(256) void ln_f16_kernel(
    const float* __restrict__ x, const float* __restrict__ g, const float* __restrict__ b,
    __half* __restrict__ y)
{
    const int row = blockIdx.x;
    const int tid = threadIdx.x;
    float4 v = ((const float4*)(x + (size_t)row * DD))[tid];

    float s  = v.x + v.y + v.z + v.w;
    float sq = v.x*v.x + v.y*v.y + v.z*v.z + v.w*v.w;
    __shared__ float red_s[8], red_q[8];
    for (int o = 16; o > 0; o >>= 1) {
        s  += __shfl_xor_sync(0xffffffffu, s,  o);
        sq += __shfl_xor_sync(0xffffffffu, sq, o);
    }
    const int wid = tid >> 5, lid = tid & 31;
    if (lid == 0) { red_s[wid] = s; red_q[wid] = sq; }
    __syncthreads();
    if (tid == 0) {
        float ts = 0.f, tq = 0.f;
        #pragma unroll
        for (int i = 0; i < 8; i++) { ts += red_s[i]; tq += red_q[i]; }
        red_s[0] = ts * (1.0f / DD);
        red_q[0] = tq * (1.0f / DD);
    }
    __syncthreads();
    const float mean = red_s[0];
    const float rstd = rsqrtf(red_q[0] - mean * mean + 1e-5f);

    const float4 gg = ((const float4*)g)[tid];
    const float4 bb = ((const float4*)b)[tid];
    float o0 = (v.x - mean) * rstd * gg.x + bb.x;
    float o1 = (v.y - mean) * rstd * gg.y + bb.y;
    float o2 = (v.z - mean) * rstd * gg.z + bb.z;
    float o3 = (v.w - mean) * rstd * gg.w + bb.w;
    __half2* py = (__half2*)(y + (size_t)row * DD);
    py[2*tid]   = __floats2half2_rn(o0, o1);
    py[2*tid+1] = __floats2half2_rn(o2, o3);
}

// ---------------- fused fp32 -> fp16 weight convert (4x ILP) --------------
#define CV0 (D3*DD/4)
#define CV1 (DD*DD/4)
#define CV2 (MLPD*DD/4)
#define CV3 (DD*MLPD/4)
#define CVT_TOT (CV0 + CV1 + CV2 + CV3)      // 3145728, multiple of 1024
__global__ __launch_bounds__(256) void cvt_all_kernel(
    const float* __restrict__ s0, __half* __restrict__ d0,
    const float* __restrict__ s1, __half* __restrict__ d1,
    const float* __restrict__ s2, __half* __restrict__ d2,
    const float* __restrict__ s3, __half* __restrict__ d3)
{
    // each block owns 1024 contiguous float4 chunks (all within one segment)
    const int base = blockIdx.x * 1024;
    const float* src; __half* dst; int off;
    if (base < CV0)                          { src = s0; dst = d0; off = 0; }
    else if (base < CV0 + CV1)               { src = s1; dst = d1; off = CV0; }
    else if (base < CV0 + CV1 + CV2)         { src = s2; dst = d2; off = CV0 + CV1; }
    else                                     { src = s3; dst = d3; off = CV0 + CV1 + CV2; }
    const int lb = base - off + threadIdx.x;
    float4 v0 = ((const float4*)src)[lb];
    float4 v1 = ((const float4*)src)[lb + 256];
    float4 v2 = ((const float4*)src)[lb + 512];
    float4 v3 = ((const float4*)src)[lb + 768];
    ((__half2*)dst)[2*(lb)]         = __floats2half2_rn(v0.x, v0.y);
    ((__half2*)dst)[2*(lb)+1]       = __floats2half2_rn(v0.z, v0.w);
    ((__half2*)dst)[2*(lb+256)]     = __floats2half2_rn(v1.x, v1.y);
    ((__half2*)dst)[2*(lb+256)+1]   = __floats2half2_rn(v1.z, v1.w);
    ((__half2*)dst)[2*(lb+512)]     = __floats2half2_rn(v2.x, v2.y);
    ((__half2*)dst)[2*(lb+512)+1]   = __floats2half2_rn(v2.z, v2.w);
    ((__half2*)dst)[2*(lb+768)]     = __floats2half2_rn(v3.x, v3.y);
    ((__half2*)dst)[2*(lb+768)+1]   = __floats2half2_rn(v3.z, v3.w);
}

// ---------------- FA2-style split-KV HMMA attention ----------------
#define AQ 64
#define CK 64
#define QS_B (AQ*144)
#define KV_B (CK*144)
#define KS_OFF QS_B
#define VS_OFF (KS_OFF + 2*KV_B)
#define ATTN_SMEM (VS_OFF + 2*KV_B)     // 46080
#define KEYS_PER_SPLIT (TT / NS)        // 512
#define CHPS (KEYS_PER_SPLIT / CK)      // 8

__global__ void __launch_bounds__(128, 4) attn_hmma_kernel(
    float* __restrict__ o_part, float* __restrict__ m_part,
    float* __restrict__ l_part, const __half* __restrict__ qkv)
{
    extern __shared__ char smem[];
    const uint32_t sb = smem_u32(smem);

    const int t = threadIdx.x;
    const int w = t >> 5, lane = t & 31;
    const int blk = blockIdx.x;
    const int sp = blk & (NS - 1);
    const int qt = (blk >> 2) & 3;
    const int h  = (blk >> 4) & (HH - 1);
    const int b  = blk >> 8;

    {
        const __half2 sc = __floats2half2_rn(0.125f, 0.125f);
        #pragma unroll
        for (int j = 0; j < 4; j++) {
            const int idx = t + j * 128;
            const int q = idx >> 3, c = idx & 7;
            const int tq = (qt * AQ + q) * STRIDE;
            uint4 raw = *(const uint4*)(qkv + (size_t)(b * TT + tq) * D3 + h * HD + c * 8);
            __half2* hp = (__half2*)&raw;
            #pragma unroll
            for (int u = 0; u < 4; u++) hp[u] = __hmul2(hp[u], sc);
            *(uint4*)(smem + q * 144 + c * 16) = raw;
        }
    }
    __syncthreads();

    uint32_t aq[4][4];
    {
        const int r = w * 16 + (lane & 15);
        #pragma unroll
        for (int ks = 0; ks < 4; ks++)
            ldmx4(aq[ks], sb + (uint32_t)(r * 144) + (ks * 2 + (lane >> 4)) * 16);
    }

    auto load_kv = [&](int k0, int s) {
        const uint32_t kb = sb + KS_OFF + s * KV_B;
        const uint32_t vb = sb + VS_OFF + s * KV_B;
        #pragma unroll
        for (int j = 0; j < 4; j++) {
            const int idx = t + j * 128;
            const int r = idx >> 3, c = idx & 7;
            const size_t g = (size_t)(b * TT + k0 + r) * D3 + h * HD + c * 8;
            cp16(kb + r * 144 + c * 16, qkv + DD + g);
            cp16(vb + r * 144 + c * 16, qkv + 2 * DD + g);
        }
        asm volatile("cp.async.commit_group;" ::: "memory");
    };

    float oacc[8][4];
    #pragma unroll
    for (int i = 0; i < 8; i++)
        #pragma unroll
        for (int j = 0; j < 4; j++) oacc[i][j] = 0.f;
    float m0 = -1e30f, m1 = -1e30f, l0 = 0.f, l1 = 0.f;

    const int k0base = sp * KEYS_PER_SPLIT;
    load_kv(k0base, 0);

    const int lb_row = (lane & 7) + ((lane >> 4) << 3);
    const int lb_kh  = (lane >> 3) & 1;
    const int vrow   = (lane & 7) + ((lane >> 3) & 1) * 8;
    const int vcol   = (lane >> 4) * 8;

    for (int cc = 0; cc < CHPS; cc++) {
        if (cc + 1 < CHPS) load_kv(k0base + (cc + 1) * CK, (cc + 1) & 1);
        else asm volatile("cp.async.commit_group;" ::: "memory");
        asm volatile("cp.async.wait_group 1;" ::: "memory");
        __syncthreads();
        const uint32_t kB = sb + KS_OFF + (cc & 1) * KV_B;
        const uint32_t vB = sb + VS_OFF + (cc & 1) * KV_B;

        // ---- S = Q K^T
        float sacc[8][4];
        #pragma unroll
        for (int i = 0; i < 8; i++)
            #pragma unroll
            for (int j = 0; j < 4; j++) sacc[i][j] = 0.f;
        #pragma unroll
        for (int ks = 0; ks < 4; ks++) {
            uint32_t b4[4][4];
            #pragma unroll
            for (int nf2 = 0; nf2 < 4; nf2++) {
                const int r = nf2 * 16 + lb_row;
                ldmx4(b4[nf2], kB + (uint32_t)(r * 144) + (ks * 2 + lb_kh) * 16);
            }
            #pragma unroll
            for (int nf2 = 0; nf2 < 4; nf2++) {
                mma_f16(sacc[2 * nf2 + 0], aq[ks], &b4[nf2][0]);
                mma_f16(sacc[2 * nf2 + 1], aq[ks], &b4[nf2][2]);
            }
        }

        // ---- register online softmax
        float mx0 = -1e30f, mx1 = -1e30f;
        #pragma unroll
        for (int nf = 0; nf < 8; nf++) {
            mx0 = fmaxf(mx0, fmaxf(sacc[nf][0], sacc[nf][1]));
            mx1 = fmaxf(mx1, fmaxf(sacc[nf][2], sacc[nf][3]));
        }
        mx0 = fmaxf(mx0, __shfl_xor_sync(0xffffffffu, mx0, 1));
        mx0 = fmaxf(mx0, __shfl_xor_sync(0xffffffffu, mx0, 2));
        mx1 = fmaxf(mx1, __shfl_xor_sync(0xffffffffu, mx1, 1));
        mx1 = fmaxf(mx1, __shfl_xor_sync(0xffffffffu, mx1, 2));
        const float mn0 = fmaxf(m0, mx0);
        const float mn1 = fmaxf(m1, mx1);
        const float cr0 = __expf(m0 - mn0);
        const float cr1 = __expf(m1 - mn1);
        m0 = mn0; m1 = mn1;

        float ls0 = 0.f, ls1 = 0.f;
        uint32_t ap[4][4];
        #pragma unroll
        for (int kp = 0; kp < 4; kp++) {
            #pragma unroll
            for (int half = 0; half < 2; half++) {
                const int nf = 2 * kp + half;
                float e0 = __expf(sacc[nf][0] - mn0);
                float e1 = __expf(sacc[nf][1] - mn0);
                float e2 = __expf(sacc[nf][2] - mn1);
                float e3 = __expf(sacc[nf][3] - mn1);
                ls0 += e0 + e1; ls1 += e2 + e3;
                __half2 p01 = __floats2half2_rn(e0, e1);
                __half2 p23 = __floats2half2_rn(e2, e3);
                ap[kp][2 * half + 0] = *(uint32_t*)&p01;
                ap[kp][2 * half + 1] = *(uint32_t*)&p23;
            }
        }
        ls0 += __shfl_xor_sync(0xffffffffu, ls0, 1);
        ls0 += __shfl_xor_sync(0xffffffffu, ls0, 2);
        ls1 += __shfl_xor_sync(0xffffffffu, ls1, 1);
        ls1 += __shfl_xor_sync(0xffffffffu, ls1, 2);
        l0 = l0 * cr0 + ls0;
        l1 = l1 * cr1 + ls1;

        #pragma unroll
        for (int nf = 0; nf < 8; nf++) {
            oacc[nf][0] *= cr0; oacc[nf][1] *= cr0;
            oacc[nf][2] *= cr1; oacc[nf][3] *= cr1;
        }

        // ---- O += P V
        #pragma unroll
        for (int kp = 0; kp < 4; kp++) {
            const int krow = kp * 16 + vrow;
            #pragma unroll
            for (int nf2 = 0; nf2 < 4; nf2++) {
                uint32_t bv[4];
                ldmx4t(bv, vB + (uint32_t)(krow * 144) + (nf2 * 16 + vcol) * 2);
                mma_f16(oacc[2 * nf2 + 0], ap[kp], &bv[0]);
                mma_f16(oacc[2 * nf2 + 1], ap[kp], &bv[2]);
            }
        }
        __syncthreads();
    }

    {
        const int r0 = w * 16 + (lane >> 2);
        const int r1 = r0 + 8;
        #pragma unroll
        for (int nf = 0; nf < 8; nf++) {
            const int d = nf * 8 + (lane & 3) * 2;
            const size_t i0 = ((((size_t)(b * NGR + qt * AQ + r0)) * HH + h) * NS + sp) * HD + d;
            const size_t i1 = ((((size_t)(b * NGR + qt * AQ + r1)) * HH + h) * NS + sp) * HD + d;
            float2 p0; p0.x = oacc[nf][0]; p0.y = oacc[nf][1];
            float2 p1; p1.x = oacc[nf][2]; p1.y = oacc[nf][3];
            *(float2*)(o_part + i0) = p0;
            *(float2*)(o_part + i1) = p1;
        }
        if ((lane & 3) == 0) {
            const size_t mi0 = (((size_t)(b * NGR + qt * AQ + r0)) * HH + h) * NS + sp;
            const size_t mi1 = (((size_t)(b * NGR + qt * AQ + r1)) * HH + h) * NS + sp;
            m_part[mi0] = m0; l_part[mi0] = l0;
            m_part[mi1] = m1; l_part[mi1] = l1;
        }
    }
}

// ---------------- attention split reduce (2 dims/thread) -------------------
__global__ __launch_bounds__(256) void attn_reduce_kernel(
    __half* __restrict__ o, const float* __restrict__ o_part,
    const float* __restrict__ m_part, const float* __restrict__ l_part)
{
    const int idx = blockIdx.x * 256 + threadIdx.x;     // BB*NGR*HH*HD/2
    const int d2 = idx & (HD / 2 - 1);                  // pair index
    const int rh = idx >> 5;                            // (b*NGR+row)*HH + h
    const int h  = rh & (HH - 1);
    const int br = rh >> 4;
    const size_t mb = (size_t)rh * NS;

    float4 mv = *(const float4*)(m_part + mb);
    float4 lv = *(const float4*)(l_part + mb);
    float mx = fmaxf(fmaxf(mv.x, mv.y), fmaxf(mv.z, mv.w));
    float w0 = __expf(mv.x - mx), w1 = __expf(mv.y - mx);
    float w2 = __expf(mv.z - mx), w3 = __expf(mv.w - mx);
    float lsum = w0 * lv.x + w1 * lv.y + w2 * lv.z + w3 * lv.w;
    const float inv = 1.0f / lsum;

    const size_t ob = (size_t)rh * NS * HD + d2 * 2;
    float2 p0 = *(const float2*)(o_part + ob);
    float2 p1 = *(const float2*)(o_part + ob + HD);
    float2 p2 = *(const float2*)(o_part + ob + 2 * HD);
    float2 p3 = *(const float2*)(o_part + ob + 3 * HD);
    float v0 = (w0 * p0.x + w1 * p1.x + w2 * p2.x + w3 * p3.x) * inv;
    float v1 = (w0 * p0.y + w1 * p1.y + w2 * p2.y + w3 * p3.y) * inv;

    const int b = br >> 8;
    const int row = br & (NGR - 1);
    *(__half2*)(o + (size_t)(b * TT + row * STRIDE) * DD + h * HD + d2 * 2) =
        __floats2half2_rn(v0, v1);
}

// ---------------- launch ----------------
extern "C" void kernel_launch(void* const* d_in, const int* in_sizes, int n_in,
                              void* d_out, int out_size)
{
    const float* x     = (const float*)d_in[0];
    const float* w_in  = (const float*)d_in[1];
    const float* b_in  = (const float*)d_in[2];
    const float* w_out = (const float*)d_in[3];
    const float* b_out = (const float*)d_in[4];
    const float* w1    = (const float*)d_in[5];
    const float* b1    = (const float*)d_in[6];
    const float* w2    = (const float*)d_in[7];
    const float* b2    = (const float*)d_in[8];
    const float* ln1_g = (const float*)d_in[9];
    const float* ln1_b = (const float*)d_in[10];
    const float* ln2_g = (const float*)d_in[11];
    const float* ln2_b = (const float*)d_in[12];
    float* out = (float*)d_out;

    __half *xn,*o,*xn2,*hbuf,*win,*wout,*w1h,*w2h,*qkv;
    float *x2, *opart, *mpart, *lpart;
    cudaGetSymbolAddress((void**)&xn,   g_xn);
    cudaGetSymbolAddress((void**)&o,    g_o);
    cudaGetSymbolAddress((void**)&xn2,  g_xn2);
    cudaGetSymbolAddress((void**)&hbuf, g_h);
    cudaGetSymbolAddress((void**)&win,  g_win);
    cudaGetSymbolAddress((void**)&wout, g_wout);
    cudaGetSymbolAddress((void**)&w1h,  g_w1);
    cudaGetSymbolAddress((void**)&w2h,  g_w2);
    cudaGetSymbolAddress((void**)&qkv,  g_qkv);
    cudaGetSymbolAddress((void**)&x2,   g_x2);
    cudaGetSymbolAddress((void**)&opart, g_opart);
    cudaGetSymbolAddress((void**)&mpart, g_mpart);
    cudaGetSymbolAddress((void**)&lpart, g_lpart);

    cudaFuncSetAttribute(qkv_kernel, cudaFuncAttributeMaxDynamicSharedMemorySize, GEMM_SMEM);
    cudaFuncSetAttribute(gemm_f16k<false,true ,false>, cudaFuncAttributeMaxDynamicSharedMemorySize, GEMM_SMEM);
    cudaFuncSetAttribute(gemm_f16k<true ,false,true >, cudaFuncAttributeMaxDynamicSharedMemorySize, GEMM_SMEM);
    cudaFuncSetAttribute(attn_hmma_kernel, cudaFuncAttributeMaxDynamicSharedMemorySize, ATTN_SMEM);

    // 1. LN1 -> f16
    ln_f16_kernel<<<BT, 256>>>(x, ln1_g, ln1_b, xn);
    // 2. convert all weights -> f16 (4x ILP)
    cvt_all_kernel<<<CVT_TOT / 1024, 256>>>(
        w_in, win, w_out, wout, w1, w1h, w2, w2h);
    // 3. QKV (kv: all rows; q: global rows only; v-copy fused)
    qkv_kernel<<<dim3(12, 32), 256, GEMM_SMEM>>>(xn, win, b_in, qkv, o);
    // 4. attention: FA2 split-KV partials + reduce
    attn_hmma_kernel<<<BB*HH*4*NS, 128, ATTN_SMEM>>>(opart, mpart, lpart, qkv);
    attn_reduce_kernel<<<(BB*NGR*HH*HD/2)/256, 256>>>(o, opart, mpart, lpart);
    // 5. out-proj + residual -> x2 fp32
    gemm_f16k<false,true,false><<<dim3(DD/GN, BT/GM), 256, GEMM_SMEM>>>(
        o, wout, b_out, x, x2, nullptr, DD, DD);
    // 6. LN2 -> f16
    ln_f16_kernel<<<BT, 256>>>(x2, ln2_g, ln2_b, xn2);
    // 7. MLP1 + GELU -> h f16
    gemm_f16k<true,false,true><<<dim3(MLPD/GN, BT/GM), 256, GEMM_SMEM>>>(
        xn2, w1h, b1, nullptr, nullptr, hbuf, MLPD, DD);
    // 8. MLP2 + residual -> out fp32
    gemm_f16k<false,true,false><<<dim3(DD/GN, BT/GM), 256, GEMM_SMEM>>>(
        hbuf, w2h, b2, x2, out, nullptr, DD, MLPD);
}